// round 3
// baseline (speedup 1.0000x reference)
#include <cuda_runtime.h>

// CTC forward loss, linear-domain with power-of-2 rescaling.
// B=512 blocks (one per batch), 128 threads (one per lattice state, S=97).
#define B_ 512
#define T_ 512
#define C_ 128
#define L_ 48
#define S_ 97
#define EPS_ 1e-7f

__global__ __launch_bounds__(128, 8) void ctc_kernel(
    const int* __restrict__ y_true,
    const float* __restrict__ y_pred,
    float* __restrict__ out)
{
    const int b    = blockIdx.x;
    const int tid  = threadIdx.x;     // 0..127
    const int lane = tid & 31;
    const int wid  = tid >> 5;        // 0..3

    __shared__ float bnd[2][4][2];    // parity double-buffered cross-warp boundary (lanes 30,31)
    __shared__ float red[4];          // per-warp partial sums for renorm
    __shared__ int   sext[128];
    __shared__ float fin[2];

    // extended label sequence: blank, l0, blank, l1, ..., blank  (blank = C-1)
    int ext = C_ - 1;
    if ((tid & 1) && tid < S_) ext = y_true[b * L_ + (tid >> 1)];
    sext[tid] = ext;
    const bool valid = (tid < S_);
    __syncthreads();

    // skip (s-2 -> s) allowed iff state is a label and differs from label two back
    float skipf = 0.f;
    if ((tid & 1) && tid >= 2 && tid < S_)
        skipf = (ext != sext[tid - 2]) ? 1.f : 0.f;

    // per-thread gather pointer into this batch's prob matrix at class ext
    const float* __restrict__ row0 = y_pred + (long long)b * T_ * C_ + ext;

    // alpha at t=0: states 0,1 get p0, rest 0
    float a = 0.f;
    if (tid < 2) a = __ldg(row0) + EPS_;

    // prefetch: prologue probs t=1..7 and ring pf[u] = prob at t=8+u
    float pp[7];
#pragma unroll
    for (int t = 1; t <= 7; ++t) pp[t - 1] = __ldg(row0 + t * C_);
    float pf[8];
#pragma unroll
    for (int u = 0; u < 8; ++u) pf[u] = __ldg(row0 + (8 + u) * C_);

    float esum = 0.f;   // accumulated base-2 exponent of the normalizers
    int   par  = 0;

#define STEP(pval)                                                           \
    do {                                                                     \
        if (lane >= 30) bnd[par][wid][lane - 30] = a;                        \
        float am1 = __shfl_up_sync(0xffffffffu, a, 1);                       \
        float am2 = __shfl_up_sync(0xffffffffu, a, 2);                       \
        __syncthreads();                                                     \
        if (lane < 2) {                                                      \
            float b1 = (wid > 0) ? bnd[par][wid - 1][1] : 0.f;               \
            float b0 = (wid > 0) ? bnd[par][wid - 1][0] : 0.f;               \
            if (lane == 0) { am1 = b1; am2 = b0; }                           \
            else           { am2 = b1; }                                     \
        }                                                                    \
        float v = (a + am1) + skipf * am2;                                   \
        a = valid ? v * ((pval) + EPS_) : 0.f;                               \
        par ^= 1;                                                            \
    } while (0)

#define RENORM()                                                             \
    do {                                                                     \
        float ws = a;                                                        \
        ws += __shfl_xor_sync(0xffffffffu, ws, 16);                          \
        ws += __shfl_xor_sync(0xffffffffu, ws, 8);                           \
        ws += __shfl_xor_sync(0xffffffffu, ws, 4);                           \
        ws += __shfl_xor_sync(0xffffffffu, ws, 2);                           \
        ws += __shfl_xor_sync(0xffffffffu, ws, 1);                           \
        if (lane == 0) red[wid] = ws;                                        \
        __syncthreads();                                                     \
        float c = (red[0] + red[1]) + (red[2] + red[3]);                     \
        int e = (__float_as_int(c) >> 23) & 255;                             \
        float scale = __int_as_float((254 - e) << 23); /* 2^(127-e) */       \
        a *= scale;                                                          \
        esum += (float)(e - 127);                                            \
    } while (0)

    // prologue: t = 1..7, then renorm
#pragma unroll
    for (int t = 1; t <= 7; ++t) STEP(pp[t - 1]);
    RENORM();

    // main loop: t = 8..511 in groups of 8, static prefetch ring, renorm each group
    for (int tb = 8; tb < T_; tb += 8) {
#pragma unroll
        for (int u = 0; u < 8; ++u) {
            float p  = pf[u];
            int   tn = tb + u + 8;
            pf[u] = (tn < T_) ? __ldg(row0 + tn * C_) : 0.f;
            STEP(p);
        }
        RENORM();
    }

    // final: -log( alpha[S-1] + alpha[S-2] ) - esum*ln2
    if (tid == S_ - 1) fin[0] = a;
    if (tid == S_ - 2) fin[1] = a;
    __syncthreads();
    if (tid == 0)
        out[b] = -(logf(fin[0] + fin[1]) + esum * 0.69314718055994531f);

#undef STEP
#undef RENORM
}

extern "C" void kernel_launch(void* const* d_in, const int* in_sizes, int n_in,
                              void* d_out, int out_size)
{
    const int*   y_true = (const int*)d_in[0];    // [512, 48] int32
    const float* y_pred = (const float*)d_in[1];  // [512, 512, 128] float32
    float*       out    = (float*)d_out;          // [512, 1] float32
    (void)in_sizes; (void)n_in; (void)out_size;
    ctc_kernel<<<B_, 128>>>(y_true, y_pred, out);
}

// round 7
// speedup vs baseline: 1.5488x; 1.5488x over previous
#include <cuda_runtime.h>

// CTC forward loss — warp-per-batch-element, 4 lattice states per lane,
// linear-probability domain with power-of-2 renormalization every 16 steps
// to a HIGH target (sum ~ 2^64) so on-schedule lattice mass never flushes.
// No __syncthreads, no shared memory: one shfl_up per time step.
#define B_ 512
#define T_ 512
#define C_ 128
#define L_ 48
#define EPS_ 1e-7f

__global__ __launch_bounds__(32) void ctc_warp_kernel(
    const int* __restrict__ y_true,
    const float* __restrict__ y_pred,
    float* __restrict__ out)
{
    const int b    = blockIdx.x;
    const int lane = threadIdx.x;           // 0..31
    const unsigned FULL = 0xffffffffu;

    const float* __restrict__ base = y_pred + (size_t)b * T_ * C_;

    // lane l owns states s = 4l .. 4l+3.  S = 97 states (0..96).
    // even states: blank (class 127). odd states 4l+1 -> label 2l, 4l+3 -> label 2l+1.
    const bool lab = (lane < 24);           // lanes with valid label states (s<=95)
    int cls1 = C_ - 1, cls3 = C_ - 1;
    if (lab) {
        cls1 = y_true[b * L_ + 2 * lane];
        cls3 = y_true[b * L_ + 2 * lane + 1];
    }
    const int prev_cls3 = __shfl_up_sync(FULL, cls3, 1);
    const float skip1 = (cls1 != prev_cls3) ? 1.f : 0.f;   // s-2 skip for state 4l+1
    const float skip3 = (cls3 != cls1)      ? 1.f : 0.f;   // s-2 skip for state 4l+3
    const float m0  = (lane <= 24) ? 1.f : 0.f;            // validity masks (renorm only)
    const float m13 = lab ? 1.f : 0.f;

    // ---- t = 0 init: alpha[0] = p_blank(0)+eps, alpha[1] = p_label0(0)+eps ----
    float a0 = 0.f, a1 = 0.f, a2 = 0.f, a3 = 0.f;
    {
        float pb0 = __ldg(base + (C_ - 1)) + EPS_;
        float pl0 = __ldg(base + cls1) + EPS_;
        if (lane == 0) { a0 = pb0; a1 = pl0; }
    }

    // one recurrence step at time t with probs (pb, pl1, pl3)
#define STEP(pb, pl1, pl3)                                                   \
    do {                                                                     \
        float p3 = __shfl_up_sync(FULL, a3, 1);                              \
        if (lane == 0) p3 = 0.f;                                             \
        float na0 = (a0 + p3) * (pb);                                        \
        float na1 = ((a1 + a0) + skip1 * p3) * (pl1);                        \
        float na2 = (a2 + a1) * (pb);                                        \
        float na3 = ((a3 + a2) + skip3 * a1) * (pl3);                        \
        a0 = na0; a1 = na1; a2 = na2; a3 = na3;                              \
    } while (0)

    // Renormalize alphas so the warp-sum lands near 2^64 (target exponent 191
    // biased): keeps the smallest relevant lattice mass ~2^77 above the
    // denormal floor even with a 16-step cadence. Scale exponent field is
    // clamped to 254 (max finite) for the transient first renorms; esum uses
    // the actually-applied scale, so the clamp is exact bookkeeping-wise.
#define RENORM()                                                             \
    do {                                                                     \
        float ws = m0 * a0 + m13 * ((a1 + a2) + a3);                         \
        ws += __shfl_xor_sync(FULL, ws, 16);                                 \
        ws += __shfl_xor_sync(FULL, ws, 8);                                  \
        ws += __shfl_xor_sync(FULL, ws, 4);                                  \
        ws += __shfl_xor_sync(FULL, ws, 2);                                  \
        ws += __shfl_xor_sync(FULL, ws, 1);                                  \
        int e = (__float_as_int(ws) >> 23) & 255;                            \
        int f = 318 - e;              /* biased exp of 2^(191-e) */          \
        f = (f > 254) ? 254 : f;                                             \
        float scale = __int_as_float(f << 23);                               \
        a0 *= scale; a1 *= scale; a2 *= scale; a3 *= scale;                  \
        esum -= (float)(f - 127);     /* true alpha = stored * 2^esum */     \
    } while (0)

    float esum = 0.f;

    // ---- prologue probs for t = 1..15 (direct regs) ----
    float ppb[15], pp1[15], pp3[15];
#pragma unroll
    for (int u = 0; u < 15; ++u) {
        const float* r = base + (u + 1) * C_;
        ppb[u] = __ldg(r + (C_ - 1)) + EPS_;
        pp1[u] = __ldg(r + cls1) + EPS_;
        pp3[u] = __ldg(r + cls3) + EPS_;
    }
    // ---- prefetch ring: 16-step lookahead, holds t = 16..31 ----
    float rb[16], r1[16], r3[16];
#pragma unroll
    for (int u = 0; u < 16; ++u) {
        const float* r = base + (16 + u) * C_;
        rb[u] = __ldg(r + (C_ - 1)) + EPS_;
        r1[u] = __ldg(r + cls1) + EPS_;
        r3[u] = __ldg(r + cls3) + EPS_;
    }

    // ---- steps t = 1..15 ----
#pragma unroll
    for (int u = 0; u < 15; ++u) STEP(ppb[u], pp1[u], pp3[u]);
    RENORM();

    // ---- main loop: t = 16..495, 30 blocks of 16, unconditional refill ----
    for (int tb = 16; tb <= 480; tb += 16) {
#pragma unroll
        for (int u = 0; u < 16; ++u) {
            float pb = rb[u], pl1 = r1[u], pl3 = r3[u];
            const float* r = base + (tb + u + 16) * C_;   // max 511: in-bounds
            rb[u] = __ldg(r + (C_ - 1)) + EPS_;
            r1[u] = __ldg(r + cls1) + EPS_;
            r3[u] = __ldg(r + cls3) + EPS_;
            STEP(pb, pl1, pl3);
        }
        RENORM();
    }

    // ---- peeled last block: t = 496..511, ring already holds it ----
#pragma unroll
    for (int u = 0; u < 16; ++u) STEP(rb[u], r1[u], r3[u]);
    RENORM();

    // ---- final: -log(alpha[S-1] + alpha[S-2]) - esum*ln2 ----
    float f0 = __shfl_sync(FULL, a0, 24);   // state 96 (final blank)
    float f1 = __shfl_sync(FULL, a3, 23);   // state 95 (last label)
    if (lane == 0)
        out[b] = -(logf(f0 + f1) + esum * 0.69314718055994531f);

#undef STEP
#undef RENORM
}

extern "C" void kernel_launch(void* const* d_in, const int* in_sizes, int n_in,
                              void* d_out, int out_size)
{
    const int*   y_true = (const int*)d_in[0];    // [512, 48] int32
    const float* y_pred = (const float*)d_in[1];  // [512, 512, 128] float32
    float*       out    = (float*)d_out;          // [512, 1] float32
    (void)in_sizes; (void)n_in; (void)out_size;
    ctc_warp_kernel<<<B_, 32>>>(y_true, y_pred, out);
}

// round 8
// speedup vs baseline: 1.5771x; 1.0183x over previous
#include <cuda_runtime.h>

// CTC forward loss — warp-per-batch-element, 4 lattice states per lane,
// linear-probability domain with power-of-2 renormalization every 16 steps
// (target sum ~2^64 so on-schedule lattice mass never flushes).
// 32-step register prefetch ring (slot = t & 31, refill t+32 into same slot)
// to cover the ~600-cycle DRAM latency at 3.5 warps/SM.
#define B_ 512
#define T_ 512
#define C_ 128
#define L_ 48
#define EPS_ 1e-7f

__global__ __launch_bounds__(32) void ctc_warp_kernel(
    const int* __restrict__ y_true,
    const float* __restrict__ y_pred,
    float* __restrict__ out)
{
    const int b    = blockIdx.x;
    const int lane = threadIdx.x;           // 0..31
    const unsigned FULL = 0xffffffffu;

    const float* __restrict__ base = y_pred + (size_t)b * T_ * C_;

    // lane l owns states s = 4l .. 4l+3.  S = 97 states (0..96).
    // even states: blank (class 127). odd states 4l+1 -> label 2l, 4l+3 -> label 2l+1.
    const bool lab = (lane < 24);           // lanes with valid label states (s<=95)
    int cls1 = C_ - 1, cls3 = C_ - 1;
    if (lab) {
        cls1 = y_true[b * L_ + 2 * lane];
        cls3 = y_true[b * L_ + 2 * lane + 1];
    }
    const int prev_cls3 = __shfl_up_sync(FULL, cls3, 1);
    const float skip1 = (cls1 != prev_cls3) ? 1.f : 0.f;   // s-2 skip for state 4l+1
    const float skip3 = (cls3 != cls1)      ? 1.f : 0.f;   // s-2 skip for state 4l+3
    const float m0  = (lane <= 24) ? 1.f : 0.f;            // validity masks (renorm only)
    const float m13 = lab ? 1.f : 0.f;

    // ---- t = 0 init: alpha[0] = p_blank(0)+eps, alpha[1] = p_label0(0)+eps ----
    float a0 = 0.f, a1 = 0.f, a2 = 0.f, a3 = 0.f;
    {
        float pb0 = __ldg(base + (C_ - 1)) + EPS_;
        float pl0 = __ldg(base + cls1) + EPS_;
        if (lane == 0) { a0 = pb0; a1 = pl0; }
    }

#define STEP(pb, pl1, pl3)                                                   \
    do {                                                                     \
        float p3 = __shfl_up_sync(FULL, a3, 1);                              \
        if (lane == 0) p3 = 0.f;                                             \
        float na0 = (a0 + p3) * (pb);                                        \
        float na1 = ((a1 + a0) + skip1 * p3) * (pl1);                        \
        float na2 = (a2 + a1) * (pb);                                        \
        float na3 = ((a3 + a2) + skip3 * a1) * (pl3);                        \
        a0 = na0; a1 = na1; a2 = na2; a3 = na3;                              \
    } while (0)

    // Renormalize so the warp-sum lands near 2^64 (scale = 2^(191-e), exact
    // power of two; exponent field clamped to 254 for the warm-up renorms).
#define RENORM()                                                             \
    do {                                                                     \
        float ws = m0 * a0 + m13 * ((a1 + a2) + a3);                         \
        ws += __shfl_xor_sync(FULL, ws, 16);                                 \
        ws += __shfl_xor_sync(FULL, ws, 8);                                  \
        ws += __shfl_xor_sync(FULL, ws, 4);                                  \
        ws += __shfl_xor_sync(FULL, ws, 2);                                  \
        ws += __shfl_xor_sync(FULL, ws, 1);                                  \
        int e = (__float_as_int(ws) >> 23) & 255;                            \
        int f = 318 - e;              /* biased exp of 2^(191-e) */          \
        f = (f > 254) ? 254 : f;                                             \
        float scale = __int_as_float(f << 23);                               \
        a0 *= scale; a1 *= scale; a2 *= scale; a3 *= scale;                  \
        esum -= (float)(f - 127);     /* true alpha = stored * 2^esum */     \
    } while (0)

#define LOADSLOT(idx, t)                                                     \
    do {                                                                     \
        const float* _r = base + (t) * C_;                                   \
        rb[idx] = __ldg(_r + (C_ - 1)) + EPS_;                               \
        r1[idx] = __ldg(_r + cls1) + EPS_;                                   \
        r3[idx] = __ldg(_r + cls3) + EPS_;                                   \
    } while (0)

    float esum = 0.f;

    // ---- 32-deep prefetch ring: slot t&31 holds probs for time t ----
    float rb[32], r1[32], r3[32];
#pragma unroll
    for (int t = 1; t <= 32; ++t) LOADSLOT(t & 31, t);   // fill t = 1..32

    // ---- prologue: t = 1..31, refill t+32 into the same slot ----
#pragma unroll
    for (int t = 1; t <= 15; ++t) {
        float pb = rb[t], pl1 = r1[t], pl3 = r3[t];
        LOADSLOT(t, t + 32);
        STEP(pb, pl1, pl3);
    }
    RENORM();
#pragma unroll
    for (int t = 16; t <= 31; ++t) {
        float pb = rb[t], pl1 = r1[t], pl3 = r3[t];
        LOADSLOT(t, t + 32);
        STEP(pb, pl1, pl3);
    }
    RENORM();

    // ---- main loop: t = 32..479 in 14 aligned 32-step chunks.
    //      Refill t+32 (last refill lands at t = 511) — all unconditional. ----
    for (int tb = 32; tb <= 448; tb += 32) {
#pragma unroll
        for (int u = 0; u < 16; ++u) {                   // t = tb+u, slot u
            float pb = rb[u], pl1 = r1[u], pl3 = r3[u];
            LOADSLOT(u, tb + u + 32);
            STEP(pb, pl1, pl3);
        }
        RENORM();
#pragma unroll
        for (int u = 0; u < 16; ++u) {                   // t = tb+16+u, slot 16+u
            float pb = rb[16 + u], pl1 = r1[16 + u], pl3 = r3[16 + u];
            LOADSLOT(16 + u, tb + u + 48);
            STEP(pb, pl1, pl3);
        }
        RENORM();
    }

    // ---- peeled tail: t = 480..511, ring already holds it ----
#pragma unroll
    for (int u = 0; u < 16; ++u) STEP(rb[u], r1[u], r3[u]);        // 480..495
    RENORM();
#pragma unroll
    for (int u = 0; u < 16; ++u) STEP(rb[16 + u], r1[16 + u], r3[16 + u]); // 496..511
    RENORM();

    // ---- final: -log(alpha[S-1] + alpha[S-2]) - esum*ln2 ----
    float f0 = __shfl_sync(FULL, a0, 24);   // state 96 (final blank)
    float f1 = __shfl_sync(FULL, a3, 23);   // state 95 (last label)
    if (lane == 0)
        out[b] = -(logf(f0 + f1) + esum * 0.69314718055994531f);

#undef STEP
#undef RENORM
#undef LOADSLOT
}

extern "C" void kernel_launch(void* const* d_in, const int* in_sizes, int n_in,
                              void* d_out, int out_size)
{
    const int*   y_true = (const int*)d_in[0];    // [512, 48] int32
    const float* y_pred = (const float*)d_in[1];  // [512, 512, 128] float32
    float*       out    = (float*)d_out;          // [512, 1] float32
    (void)in_sizes; (void)n_in; (void)out_size;
    ctc_warp_kernel<<<B_, 32>>>(y_true, y_pred, out);
}

// round 9
// speedup vs baseline: 2.3535x; 1.4923x over previous
#include <cuda_runtime.h>
#include <cstdint>

// CTC forward loss — warp-per-batch-element, 4 lattice states per lane.
// Linear-probability domain, power-of-2 renorm every 16 steps (target ~2^64).
// Memory: cp.async.bulk copies 16 full prob rows (8KB, contiguous) per chunk
// into a 4-deep smem ring; per-step class gather is done with LDS (smem),
// eliminating the scattered-LDG L1tex wavefront-queue bottleneck of R8.
#define B_ 512
#define T_ 512
#define C_ 128
#define L_ 48
#define EPS_ 1e-7f

#define STEPS_PER_CHUNK 16
#define NCHUNK (T_ / STEPS_PER_CHUNK)      // 32
#define RING 4                              // smem ring depth (chunks)
#define CHUNK_FLOATS (STEPS_PER_CHUNK * C_) // 2048
#define CHUNK_BYTES  (CHUNK_FLOATS * 4)     // 8192

__global__ __launch_bounds__(32) void ctc_warp_kernel(
    const int* __restrict__ y_true,
    const float* __restrict__ y_pred,
    float* __restrict__ out)
{
    __shared__ __align__(128) float ring[RING][CHUNK_FLOATS];   // 32 KB
    __shared__ __align__(8)  uint64_t mbar[RING];

    const int b    = blockIdx.x;
    const int lane = threadIdx.x;           // 0..31
    const unsigned FULL = 0xffffffffu;

    const float* __restrict__ base = y_pred + (size_t)b * T_ * C_;

    // smem addresses (u32, shared window)
    uint32_t ring_u32, mbar_u32;
    {
        uint64_t t0, t1;
        asm ("cvta.to.shared.u64 %0, %1;" : "=l"(t0) : "l"(&ring[0][0]));
        asm ("cvta.to.shared.u64 %0, %1;" : "=l"(t1) : "l"(&mbar[0]));
        ring_u32 = (uint32_t)t0;
        mbar_u32 = (uint32_t)t1;
    }

    // ---- lattice wiring: lane l owns states 4l..4l+3 (S = 97) ----
    const bool lab = (lane < 24);
    int cls1 = C_ - 1, cls3 = C_ - 1;
    if (lab) {
        cls1 = y_true[b * L_ + 2 * lane];
        cls3 = y_true[b * L_ + 2 * lane + 1];
    }
    const int prev_cls3 = __shfl_up_sync(FULL, cls3, 1);
    const float skip1 = (cls1 != prev_cls3) ? 1.f : 0.f;
    const float skip3 = (cls3 != cls1)      ? 1.f : 0.f;
    const float m0  = (lane <= 24) ? 1.f : 0.f;
    const float m13 = lab ? 1.f : 0.f;

    // ---- mbarrier init + first RING bulk copies (lane 0) ----
    if (lane == 0) {
#pragma unroll
        for (int s = 0; s < RING; ++s)
            asm volatile("mbarrier.init.shared.b64 [%0], %1;"
                         :: "r"(mbar_u32 + 8u * s), "r"(1) : "memory");
        asm volatile("fence.proxy.async.shared::cta;" ::: "memory");
#pragma unroll
        for (int c = 0; c < RING; ++c) {
            uint32_t bar = mbar_u32 + 8u * c;
            uint32_t dst = ring_u32 + (uint32_t)(c * CHUNK_BYTES);
            const float* src = base + (size_t)c * CHUNK_FLOATS;
            asm volatile("mbarrier.arrive.expect_tx.shared.b64 _, [%0], %1;"
                         :: "r"(bar), "r"(CHUNK_BYTES) : "memory");
            asm volatile(
                "cp.async.bulk.shared::cluster.global.mbarrier::complete_tx::bytes "
                "[%0], [%1], %2, [%3];"
                :: "r"(dst), "l"(src), "r"(CHUNK_BYTES), "r"(bar) : "memory");
        }
    }
    __syncwarp();

#define MBWAIT(addr, ph)                                                     \
    do {                                                                     \
        unsigned _done = 0;                                                  \
        while (!_done) {                                                     \
            asm volatile(                                                    \
                "{\n\t.reg .pred p;\n\t"                                     \
                "mbarrier.try_wait.parity.acquire.cta.shared::cta.b64 p, [%1], %2, 0x989680;\n\t" \
                "selp.b32 %0, 1, 0, p;\n\t}"                                 \
                : "=r"(_done) : "r"(addr), "r"(ph) : "memory");              \
        }                                                                    \
    } while (0)

#define STEP(pb, pl1, pl3)                                                   \
    do {                                                                     \
        float p3 = __shfl_up_sync(FULL, a3, 1);                              \
        if (lane == 0) p3 = 0.f;                                             \
        float na0 = (a0 + p3) * (pb);                                        \
        float na1 = ((a1 + a0) + skip1 * p3) * (pl1);                        \
        float na2 = (a2 + a1) * (pb);                                        \
        float na3 = ((a3 + a2) + skip3 * a1) * (pl3);                        \
        a0 = na0; a1 = na1; a2 = na2; a3 = na3;                              \
    } while (0)

    // Renorm warp-sum to ~2^64: scale = 2^(191-e) exact, exponent clamped.
#define RENORM()                                                             \
    do {                                                                     \
        float ws = m0 * a0 + m13 * ((a1 + a2) + a3);                         \
        ws += __shfl_xor_sync(FULL, ws, 16);                                 \
        ws += __shfl_xor_sync(FULL, ws, 8);                                  \
        ws += __shfl_xor_sync(FULL, ws, 4);                                  \
        ws += __shfl_xor_sync(FULL, ws, 2);                                  \
        ws += __shfl_xor_sync(FULL, ws, 1);                                  \
        int e = (__float_as_int(ws) >> 23) & 255;                            \
        int f = 318 - e;                                                     \
        f = (f > 254) ? 254 : f;                                             \
        float scale = __int_as_float(f << 23);                               \
        a0 *= scale; a1 *= scale; a2 *= scale; a3 *= scale;                  \
        esum -= (float)(f - 127);                                            \
    } while (0)

    float a0 = 0.f, a1 = 0.f, a2 = 0.f, a3 = 0.f;
    float esum = 0.f;

    // ---- chunk 0: init at t=0, then steps t = 1..15 ----
    {
        MBWAIT(mbar_u32, 0);
        const float* row0 = &ring[0][0];
        float pb0 = row0[C_ - 1] + EPS_;
        float pl0 = row0[cls1] + EPS_;
        if (lane == 0) { a0 = pb0; a1 = pl0; }
#pragma unroll
        for (int u = 1; u < STEPS_PER_CHUNK; ++u) {
            const float* row = &ring[0][u * C_];
            float pb  = row[C_ - 1] + EPS_;
            float pl1 = row[cls1] + EPS_;
            float pl3 = row[cls3] + EPS_;
            STEP(pb, pl1, pl3);
        }
        RENORM();
        // refill slot 0 with chunk RING (c = 4)
        if (lane == 0) {
            uint32_t bar = mbar_u32;
            uint32_t dst = ring_u32;
            const float* src = base + (size_t)RING * CHUNK_FLOATS;
            asm volatile("mbarrier.arrive.expect_tx.shared.b64 _, [%0], %1;"
                         :: "r"(bar), "r"(CHUNK_BYTES) : "memory");
            asm volatile(
                "cp.async.bulk.shared::cluster.global.mbarrier::complete_tx::bytes "
                "[%0], [%1], %2, [%3];"
                :: "r"(dst), "l"(src), "r"(CHUNK_BYTES), "r"(bar) : "memory");
        }
    }

    // ---- chunks 1..31 ----
    for (int c = 1; c < NCHUNK; ++c) {
        const int s  = c & (RING - 1);
        const int ph = (c >> 2) & 1;
        const uint32_t bar = mbar_u32 + 8u * s;
        MBWAIT(bar, ph);
        const float* chunk = &ring[s][0];
#pragma unroll
        for (int u = 0; u < STEPS_PER_CHUNK; ++u) {
            const float* row = chunk + u * C_;
            float pb  = row[C_ - 1] + EPS_;
            float pl1 = row[cls1] + EPS_;
            float pl3 = row[cls3] + EPS_;
            STEP(pb, pl1, pl3);
        }
        RENORM();
        if (c < NCHUNK - RING && lane == 0) {
            uint32_t dst = ring_u32 + (uint32_t)(s * CHUNK_BYTES);
            const float* src = base + (size_t)(c + RING) * CHUNK_FLOATS;
            asm volatile("mbarrier.arrive.expect_tx.shared.b64 _, [%0], %1;"
                         :: "r"(bar), "r"(CHUNK_BYTES) : "memory");
            asm volatile(
                "cp.async.bulk.shared::cluster.global.mbarrier::complete_tx::bytes "
                "[%0], [%1], %2, [%3];"
                :: "r"(dst), "l"(src), "r"(CHUNK_BYTES), "r"(bar) : "memory");
        }
    }

    // ---- final: -log(alpha[S-1] + alpha[S-2]) - esum*ln2 ----
    float f0 = __shfl_sync(FULL, a0, 24);   // state 96 (final blank)
    float f1 = __shfl_sync(FULL, a3, 23);   // state 95 (last label)
    if (lane == 0)
        out[b] = -(logf(f0 + f1) + esum * 0.69314718055994531f);

#undef STEP
#undef RENORM
#undef MBWAIT
}

extern "C" void kernel_launch(void* const* d_in, const int* in_sizes, int n_in,
                              void* d_out, int out_size)
{
    const int*   y_true = (const int*)d_in[0];    // [512, 48] int32
    const float* y_pred = (const float*)d_in[1];  // [512, 512, 128] float32
    float*       out    = (float*)d_out;          // [512, 1] float32
    (void)in_sizes; (void)n_in; (void)out_size;
    ctc_warp_kernel<<<B_, 32>>>(y_true, y_pred, out);
}

// round 11
// speedup vs baseline: 2.3591x; 1.0024x over previous
#include <cuda_runtime.h>
#include <cstdint>

// CTC forward loss — warp-per-batch-element, 4 lattice states per lane.
// Linear-probability domain, power-of-2 renorm every 16 steps (target ~2^64),
// renorm via redux.sync.max.u32 on the alpha bit patterns (non-negative
// floats are bit-monotone; exponent(max) is within 7 of exponent(sum), and
// esum bookkeeping uses the actually-applied scale, so this is exact).
// Memory: cp.async.bulk streams 32 full prob rows (16KB contiguous) per chunk
// into a 3-deep dynamic-smem ring; per-step class gather is LDS with a
// distance-2 software pipeline so shared-memory latency never hits the
// serial alpha-recurrence chain.
#define B_ 512
#define T_ 512
#define C_ 128
#define L_ 48
#define EPS_ 1e-7f

#define ROWS_PER_CHUNK 32
#define NCHUNK (T_ / ROWS_PER_CHUNK)            // 16
#define RING 3
#define CHUNK_FLOATS (ROWS_PER_CHUNK * C_)       // 4096
#define CHUNK_BYTES  (CHUNK_FLOATS * 4)          // 16384
#define SMEM_TOTAL (RING * CHUNK_BYTES + 64)     // ring + mbarriers

extern __shared__ __align__(128) char dsm[];

__global__ __launch_bounds__(32) void ctc_warp_kernel(
    const int* __restrict__ y_true,
    const float* __restrict__ y_pred,
    float* __restrict__ out)
{
    float*    ring = (float*)dsm;                         // 3 x 16KB
    uint64_t* mbar = (uint64_t*)(dsm + RING * CHUNK_BYTES);

    const int b    = blockIdx.x;
    const int lane = threadIdx.x;
    const unsigned FULL = 0xffffffffu;

    const float* __restrict__ base = y_pred + (size_t)b * T_ * C_;

    uint32_t ring_u32, mbar_u32;
    {
        uint64_t t0, t1;
        asm ("cvta.to.shared.u64 %0, %1;" : "=l"(t0) : "l"(ring));
        asm ("cvta.to.shared.u64 %0, %1;" : "=l"(t1) : "l"(mbar));
        ring_u32 = (uint32_t)t0;
        mbar_u32 = (uint32_t)t1;
    }

    // ---- lattice wiring: lane l owns states 4l..4l+3 (S = 97) ----
    const bool lab = (lane < 24);
    int cls1 = C_ - 1, cls3 = C_ - 1;
    if (lab) {
        cls1 = y_true[b * L_ + 2 * lane];
        cls3 = y_true[b * L_ + 2 * lane + 1];
    }
    const int prev_cls3 = __shfl_up_sync(FULL, cls3, 1);
    const float skip1 = (cls1 != prev_cls3) ? 1.f : 0.f;
    const float skip3 = (cls3 != cls1)      ? 1.f : 0.f;
    const float m0  = (lane <= 24) ? 1.f : 0.f;
    const float m13 = lab ? 1.f : 0.f;

#define ISSUE_COPY(slot, chunk_idx)                                          \
    do {                                                                     \
        uint32_t _bar = mbar_u32 + 8u * (slot);                              \
        uint32_t _dst = ring_u32 + (uint32_t)((slot) * CHUNK_BYTES);         \
        const float* _src = base + (size_t)(chunk_idx) * CHUNK_FLOATS;       \
        asm volatile("mbarrier.arrive.expect_tx.shared.b64 _, [%0], %1;"     \
                     :: "r"(_bar), "r"(CHUNK_BYTES) : "memory");             \
        asm volatile(                                                        \
            "cp.async.bulk.shared::cluster.global.mbarrier::complete_tx::bytes " \
            "[%0], [%1], %2, [%3];"                                          \
            :: "r"(_dst), "l"(_src), "r"(CHUNK_BYTES), "r"(_bar) : "memory");\
    } while (0)

    // ---- mbarrier init + first RING bulk copies (lane 0) ----
    if (lane == 0) {
#pragma unroll
        for (int s = 0; s < RING; ++s)
            asm volatile("mbarrier.init.shared.b64 [%0], %1;"
                         :: "r"(mbar_u32 + 8u * s), "r"(1) : "memory");
        asm volatile("fence.proxy.async.shared::cta;" ::: "memory");
#pragma unroll
        for (int c = 0; c < RING; ++c) ISSUE_COPY(c, c);
    }
    __syncwarp();

#define MBWAIT(addr, ph)                                                     \
    do {                                                                     \
        unsigned _done = 0;                                                  \
        while (!_done) {                                                     \
            asm volatile(                                                    \
                "{\n\t.reg .pred p;\n\t"                                     \
                "mbarrier.try_wait.parity.acquire.cta.shared::cta.b64 p, [%1], %2, 0x989680;\n\t" \
                "selp.b32 %0, 1, 0, p;\n\t}"                                 \
                : "=r"(_done) : "r"(addr), "r"(ph) : "memory");              \
        }                                                                    \
    } while (0)

#define STEP(pb, pl1, pl3)                                                   \
    do {                                                                     \
        float p3 = __shfl_up_sync(FULL, a3, 1);                              \
        if (lane == 0) p3 = 0.f;                                             \
        float na0 = (a0 + p3) * (pb);                                        \
        float na1 = ((a1 + a0) + skip1 * p3) * (pl1);                        \
        float na2 = (a2 + a1) * (pb);                                        \
        float na3 = ((a3 + a2) + skip3 * a1) * (pl3);                        \
        a0 = na0; a1 = na1; a2 = na2; a3 = na3;                              \
    } while (0)

    // Renorm: scale = 2^(191 - e_max), exact power of two; e_max from a
    // single redux.sync.max.u32 over the per-lane max alpha bit pattern
    // (valid lanes only — masked lanes contribute 0).
#define RENORM()                                                             \
    do {                                                                     \
        float w0 = m0 * a0;                                                  \
        float w1 = m13 * fmaxf(fmaxf(a1, a2), a3);                           \
        unsigned wb = __float_as_uint(fmaxf(w0, w1));                        \
        unsigned wm;                                                         \
        asm volatile("redux.sync.max.u32 %0, %1, 0xffffffff;"                \
                     : "=r"(wm) : "r"(wb));                                  \
        int e = (int)(wm >> 23) & 255;                                       \
        int f = 318 - e;                                                     \
        f = (f > 254) ? 254 : f;                                             \
        float scale = __int_as_float(f << 23);                               \
        a0 *= scale; a1 *= scale; a2 *= scale; a3 *= scale;                  \
        esum -= (float)(f - 127);                                            \
    } while (0)

#define LOADROW(dst_b, dst_1, dst_3, rowptr)                                 \
    do {                                                                     \
        const float* _rp = (rowptr);                                         \
        dst_b = _rp[C_ - 1] + EPS_;                                          \
        dst_1 = _rp[cls1] + EPS_;                                            \
        dst_3 = _rp[cls3] + EPS_;                                            \
    } while (0)

    float a0 = 0.f, a1 = 0.f, a2 = 0.f, a3 = 0.f;
    float esum = 0.f;

    // ================= chunk 0: t = 0 init + steps 1..31 =================
    {
        MBWAIT(mbar_u32, 0);
        const float* ch = ring;                    // slot 0
        // t = 0 init
        {
            float pb0 = ch[C_ - 1] + EPS_;
            float pl0 = ch[cls1] + EPS_;
            if (lane == 0) { a0 = pb0; a1 = pl0; }
        }
        // distance-2 pipelined steps t = 1..31
        float pbA, p1A, p3A, pbB, p1B, p3B, pbC, p1C, p3C;
        LOADROW(pbA, p1A, p3A, ch + 1 * C_);
        LOADROW(pbB, p1B, p3B, ch + 2 * C_);
#pragma unroll
        for (int u = 1; u <= 31; ++u) {
            if (u + 2 <= 31) LOADROW(pbC, p1C, p3C, ch + (u + 2) * C_);
            STEP(pbA, p1A, p3A);
            pbA = pbB; p1A = p1B; p3A = p3B;
            pbB = pbC; p1B = p1C; p3B = p3C;
            if (u == 15 || u == 31) RENORM();
        }
        __syncwarp();
        if (lane == 0) ISSUE_COPY(0, RING);        // chunk 3 -> slot 0
    }

    // ================= chunks 1..15 =================
    int s = 1;                                     // slot of chunk c
    for (int c = 1; c < NCHUNK; ++c) {
        const int ph = (c / RING) & 1;
        const uint32_t bar = mbar_u32 + 8u * s;
        MBWAIT(bar, ph);
        const float* ch = ring + s * CHUNK_FLOATS;

        float pbA, p1A, p3A, pbB, p1B, p3B, pbC, p1C, p3C;
        LOADROW(pbA, p1A, p3A, ch);
        LOADROW(pbB, p1B, p3B, ch + C_);
#pragma unroll
        for (int u = 0; u < 32; ++u) {
            if (u + 2 < 32) LOADROW(pbC, p1C, p3C, ch + (u + 2) * C_);
            STEP(pbA, p1A, p3A);
            pbA = pbB; p1A = p1B; p3A = p3B;
            pbB = pbC; p1B = p1C; p3B = p3C;
            if (u == 15 || u == 31) RENORM();
        }
        __syncwarp();
        if (c + RING < NCHUNK && lane == 0) ISSUE_COPY(s, c + RING);
        s = (s == RING - 1) ? 0 : s + 1;
    }

    // ---- final: -log(alpha[S-1] + alpha[S-2]) - esum*ln2 ----
    float f0 = __shfl_sync(FULL, a0, 24);   // state 96 (final blank)
    float f1 = __shfl_sync(FULL, a3, 23);   // state 95 (last label)
    if (lane == 0)
        out[b] = -(logf(f0 + f1) + esum * 0.69314718055994531f);

#undef STEP
#undef RENORM
#undef MBWAIT
#undef LOADROW
#undef ISSUE_COPY
}

extern "C" void kernel_launch(void* const* d_in, const int* in_sizes, int n_in,
                              void* d_out, int out_size)
{
    const int*   y_true = (const int*)d_in[0];    // [512, 48] int32
    const float* y_pred = (const float*)d_in[1];  // [512, 512, 128] float32
    float*       out    = (float*)d_out;          // [512, 1] float32
    (void)in_sizes; (void)n_in; (void)out_size;

    cudaFuncSetAttribute(ctc_warp_kernel,
                         cudaFuncAttributeMaxDynamicSharedMemorySize,
                         SMEM_TOTAL);
    ctc_warp_kernel<<<B_, 32, SMEM_TOTAL>>>(y_true, y_pred, out);
}

// round 12
// speedup vs baseline: 2.3818x; 1.0096x over previous
#include <cuda_runtime.h>
#include <cstdint>

// CTC forward loss — warp-per-batch-element, 4 lattice states per lane.
// Linear-probability domain, power-of-2 renorm every 16 steps (target ~2^64),
// renorm exponent from redux.sync.max.u32 over alpha bit patterns (exact:
// esum bookkeeping uses the actually-applied power-of-2 scale).
// Memory: per-8-row cp.async.cg groups (each lane copies 16B -> warp covers
// the full 512B row, perfectly coalesced) into a 64-row smem ring with
// commit_group/wait_group pipelining: ~7 groups (28KB) per warp continuously
// in flight, refill every 8 rows — fine-grained pacing vs R11's 16KB TMA
// chunks, targeting higher sustained DRAM utilization.
#define B_ 512
#define T_ 512
#define C_ 128
#define L_ 48
#define EPS_ 1e-7f

#define GROUP 8                         // rows per cp.async group (4KB)
#define NGROUPS (T_ / GROUP)            // 64
#define RING_ROWS 64                    // smem ring: 64 rows = 32KB (8 groups)

__global__ __launch_bounds__(32) void ctc_warp_kernel(
    const int* __restrict__ y_true,
    const float* __restrict__ y_pred,
    float* __restrict__ out)
{
    __shared__ __align__(128) float ring[RING_ROWS * C_];   // 32 KB

    const int b    = blockIdx.x;
    const int lane = threadIdx.x;
    const unsigned FULL = 0xffffffffu;

    const float* __restrict__ base = y_pred + (size_t)b * T_ * C_;

    uint32_t ring_u32;
    {
        uint64_t t0;
        asm ("cvta.to.shared.u64 %0, %1;" : "=l"(t0) : "l"(ring));
        ring_u32 = (uint32_t)t0;
    }
    const uint32_t my_dst_off = ring_u32 + (uint32_t)(lane << 4); // lane's 16B slot

    // ---- lattice wiring: lane l owns states 4l..4l+3 (S = 97) ----
    const bool lab = (lane < 24);
    int cls1 = C_ - 1, cls3 = C_ - 1;
    if (lab) {
        cls1 = y_true[b * L_ + 2 * lane];
        cls3 = y_true[b * L_ + 2 * lane + 1];
    }
    const int prev_cls3 = __shfl_up_sync(FULL, cls3, 1);
    const float skip1 = (cls1 != prev_cls3) ? 1.f : 0.f;
    const float skip3 = (cls3 != cls1)      ? 1.f : 0.f;
    const float m0  = (lane <= 24) ? 1.f : 0.f;
    const float m13 = lab ? 1.f : 0.f;

    // issue one 8-row group (rows g*8 .. g*8+7), then commit
#define ISSUE_GROUP(g_)                                                      \
    do {                                                                     \
        int _row0 = (g_) * GROUP;                                            \
        _Pragma("unroll")                                                    \
        for (int _r = 0; _r < GROUP; ++_r) {                                 \
            int _row = _row0 + _r;                                           \
            uint32_t _dst = my_dst_off + (uint32_t)((_row & (RING_ROWS-1)) << 9); \
            const float* _src = base + (size_t)_row * C_ + (lane << 2);      \
            asm volatile("cp.async.cg.shared.global [%0], [%1], 16;"         \
                         :: "r"(_dst), "l"(_src) : "memory");                \
        }                                                                    \
        asm volatile("cp.async.commit_group;" ::: "memory");                 \
    } while (0)

#define STEP(pb, pl1, pl3)                                                   \
    do {                                                                     \
        float p3 = __shfl_up_sync(FULL, a3, 1);                              \
        if (lane == 0) p3 = 0.f;                                             \
        float na0 = (a0 + p3) * (pb);                                        \
        float na1 = ((a1 + a0) + skip1 * p3) * (pl1);                        \
        float na2 = (a2 + a1) * (pb);                                        \
        float na3 = ((a3 + a2) + skip3 * a1) * (pl3);                        \
        a0 = na0; a1 = na1; a2 = na2; a3 = na3;                              \
    } while (0)

    // Renorm: scale = 2^(191 - e_max), exact power of two.
#define RENORM()                                                             \
    do {                                                                     \
        float w0 = m0 * a0;                                                  \
        float w1 = m13 * fmaxf(fmaxf(a1, a2), a3);                           \
        unsigned wb = __float_as_uint(fmaxf(w0, w1));                        \
        unsigned wm;                                                         \
        asm volatile("redux.sync.max.u32 %0, %1, 0xffffffff;"                \
                     : "=r"(wm) : "r"(wb));                                  \
        int e = (int)(wm >> 23) & 255;                                       \
        int f = 318 - e;                                                     \
        f = (f > 254) ? 254 : f;                                             \
        float scale = __int_as_float(f << 23);                               \
        a0 *= scale; a1 *= scale; a2 *= scale; a3 *= scale;                  \
        esum -= (float)(f - 127);                                            \
    } while (0)

    // consume the 8 rows of group g_ (skipping row 0 handling — see chunk 0)
#define CONSUME8(g_)                                                         \
    do {                                                                     \
        int _row0 = (g_) * GROUP;                                            \
        _Pragma("unroll")                                                    \
        for (int _u = 0; _u < GROUP; ++_u) {                                 \
            int _t = _row0 + _u;                                             \
            const float* _rp = ring + ((_t & (RING_ROWS-1)) * C_);           \
            float _pb  = _rp[C_ - 1] + EPS_;                                 \
            float _p1  = _rp[cls1] + EPS_;                                   \
            float _p3  = _rp[cls3] + EPS_;                                   \
            STEP(_pb, _p1, _p3);                                             \
        }                                                                    \
    } while (0)

#define WAITG(K)                                                             \
    do {                                                                     \
        asm volatile("cp.async.wait_group %0;" :: "n"(K) : "memory");        \
        __syncwarp();                                                        \
    } while (0)

    float a0 = 0.f, a1 = 0.f, a2 = 0.f, a3 = 0.f;
    float esum = 0.f;

    // ---- prologue: issue groups 0..6 (7 groups, 28KB in flight) ----
#pragma unroll
    for (int g = 0; g < 7; ++g) ISSUE_GROUP(g);

    // ---- group 0: t=0 init + steps 1..7 ----
    {
        WAITG(6);
        const float* rp = ring;                 // row 0 at slot 0
        float pb0 = rp[C_ - 1] + EPS_;
        float pl0 = rp[cls1] + EPS_;
        if (lane == 0) { a0 = pb0; a1 = pl0; }
#pragma unroll
        for (int t = 1; t < GROUP; ++t) {
            const float* r = ring + t * C_;
            float pb  = r[C_ - 1] + EPS_;
            float p1  = r[cls1] + EPS_;
            float p3  = r[cls3] + EPS_;
            STEP(pb, p1, p3);
        }
        ISSUE_GROUP(7);
    }

    // ---- main loop: groups 1..56 (issue g+7 each time; last issue = 63) ----
    for (int g = 1; g <= 56; ++g) {
        WAITG(6);
        CONSUME8(g);
        if (g & 1) RENORM();                    // after t = 16k+15
        ISSUE_GROUP(g + 7);
    }

    // ---- tail: groups 57..63, decreasing wait counts, no more issues ----
#define TAILG(g_, K_)                                                        \
    do { WAITG(K_); CONSUME8(g_); if ((g_) & 1) RENORM(); } while (0)
    TAILG(57, 6);
    TAILG(58, 5);
    TAILG(59, 4);
    TAILG(60, 3);
    TAILG(61, 2);
    TAILG(62, 1);
    TAILG(63, 0);
#undef TAILG

    // ---- final: -log(alpha[S-1] + alpha[S-2]) - esum*ln2 ----
    float f0 = __shfl_sync(FULL, a0, 24);   // state 96 (final blank)
    float f1 = __shfl_sync(FULL, a3, 23);   // state 95 (last label)
    if (lane == 0)
        out[b] = -(logf(f0 + f1) + esum * 0.69314718055994531f);

#undef STEP
#undef RENORM
#undef CONSUME8
#undef ISSUE_GROUP
#undef WAITG
}

extern "C" void kernel_launch(void* const* d_in, const int* in_sizes, int n_in,
                              void* d_out, int out_size)
{
    const int*   y_true = (const int*)d_in[0];    // [512, 48] int32
    const float* y_pred = (const float*)d_in[1];  // [512, 512, 128] float32
    float*       out    = (float*)d_out;          // [512, 1] float32
    (void)in_sizes; (void)n_in; (void)out_size;
    ctc_warp_kernel<<<B_, 32>>>(y_true, y_pred, out);
}